// round 11
// baseline (speedup 1.0000x reference)
#include <cuda_runtime.h>
#include <cuda_bf16.h>
#include <cuda_fp8.h>
#include <cstdint>

#define BATCH 4096
#define NVIEW 2
#define DIM   512
#define NTOT  8192
#define NCLS  1000

#define C_EXP  20.60992915555662f   // log2(e)/0.07
#define INV_T  14.285714285714286f  // 1/0.07
#define EBIAS  10.0f
#define ESCALE 1024.0f              // 2^EBIAS

#define NTILES_TOTAL 2080

// ---------------- smem layout (bytes) ----------------
#define A_STRIDE   528                 // 512 fp8 + 16 pad per row -> conflict-free ldmatrix
#define TILE_BYTES (128 * A_STRIDE)    // 67584
#define OFF_A      0
#define OFF_B      TILE_BYTES          // two full-K B stages
#define OFF_RED    (OFF_B + 2 * TILE_BYTES)   // 202752  (also class_sum list / finalize wsum)
#define OFF_MBAR   (OFF_RED + 4 * 128 * 4)    // 204800
#define SMEM_TOTAL (OFF_MBAR + 16)            // 204816

// ---------------- scratch ----------------
__device__ __align__(16) __nv_bfloat16 g_A[(size_t)NTOT * DIM];
__device__ __align__(16) uint8_t       g_A8[(size_t)NTOT * DIM];
__device__ __align__(16) float         g_Ssum[NCLS * DIM];
__device__ float g_Z[NTOT];
__device__ float g_sum;
__device__ int   g_cnt[NCLS];
__device__ unsigned g_bar;              // monotonic grid-sync ticket counter (never reset)

// ---------------- PTX helpers ----------------
__device__ __forceinline__ void ldm4(uint32_t r[4], uint32_t addr) {
    asm volatile("ldmatrix.sync.aligned.m8n8.x4.shared.b16 {%0,%1,%2,%3}, [%4];"
        : "=r"(r[0]), "=r"(r[1]), "=r"(r[2]), "=r"(r[3]) : "r"(addr));
}
__device__ __forceinline__ void qmma(float c[4], const uint32_t a[4], const uint32_t b[2]) {
    asm volatile("mma.sync.aligned.m16n8k32.row.col.f32.e4m3.e4m3.f32 "
        "{%0,%1,%2,%3}, {%4,%5,%6,%7}, {%8,%9}, {%0,%1,%2,%3};"
        : "+f"(c[0]), "+f"(c[1]), "+f"(c[2]), "+f"(c[3])
        : "r"(a[0]), "r"(a[1]), "r"(a[2]), "r"(a[3]), "r"(b[0]), "r"(b[1]));
}
__device__ __forceinline__ uint32_t smem_u32(const void* p) {
    uint32_t a;
    asm("{ .reg .u64 t; cvta.to.shared.u64 t, %1; cvt.u32.u64 %0, t; }" : "=r"(a) : "l"(p));
    return a;
}
__device__ __forceinline__ void bulk_cp(uint32_t dst, const void* src, uint32_t bytes, uint32_t mbar) {
    asm volatile("cp.async.bulk.shared::cta.global.mbarrier::complete_tx::bytes [%0], [%1], %2, [%3];"
        :: "r"(dst), "l"(src), "r"(bytes), "r"(mbar) : "memory");
}
__device__ __forceinline__ void mbar_init(uint32_t mbar, uint32_t cnt) {
    asm volatile("mbarrier.init.shared.b64 [%0], %1;" :: "r"(mbar), "r"(cnt) : "memory");
}
__device__ __forceinline__ void mbar_expect(uint32_t mbar, uint32_t bytes) {
    asm volatile("mbarrier.arrive.expect_tx.shared.b64 _, [%0], %1;" :: "r"(mbar), "r"(bytes) : "memory");
}
__device__ __forceinline__ void mbar_wait(uint32_t mbar, uint32_t parity) {
    uint32_t done;
    asm volatile("{ .reg .pred p; mbarrier.try_wait.parity.acquire.cta.shared::cta.b64 p, [%1], %2; selp.b32 %0, 1, 0, p; }"
        : "=r"(done) : "r"(mbar), "r"(parity) : "memory");
    if (!done) {
        asm volatile("{ .reg .pred P1;\n"
            "W_%=: mbarrier.try_wait.parity.acquire.cta.shared::cta.b64 P1, [%0], %1, 0x989680;\n"
            "@P1 bra.uni D_%=;\n bra.uni W_%=;\n D_%=: }"
            :: "r"(mbar), "r"(parity) : "memory");
    }
}
__device__ __forceinline__ uint32_t pack_h2(float lo, float hi) {
    uint32_t h;
    asm("cvt.rn.f16x2.f32 %0, %1, %2;" : "=r"(h) : "f"(hi), "f"(lo));
    return h;
}
__device__ __forceinline__ uint32_t ex2_h2(uint32_t x) {
    uint32_t e;
    asm("ex2.approx.f16x2 %0, %1;" : "=r"(e) : "r"(x));
    return e;
}
__device__ __forceinline__ uint32_t hadd2(uint32_t a, uint32_t b) {
    uint32_t d;
    asm("add.rn.f16x2 %0, %1, %2;" : "=r"(d) : "r"(a), "r"(b));
    return d;
}
__device__ __forceinline__ float2 h2_to_f2(uint32_t h) {
    float lo, hi;
    asm("{ .reg .f16 l, hh; mov.b32 {l, hh}, %2; cvt.f32.f16 %0, l; cvt.f32.f16 %1, hh; }"
        : "=f"(lo), "=f"(hi) : "r"(h));
    return make_float2(lo, hi);
}
// flattened upper-triangle tile list: iblk<32 -> c in [0,33), else c in [0,32)
__device__ __forceinline__ void decode_tile(int g, int& ib, int& c) {
    if (g < 1056) { ib = g / 33; c = g - ib * 33; }
    else { int h = g - 1056; ib = 32 + (h >> 5); c = h & 31; }
}
// monotonic-ticket grid sync (all CTAs co-resident; counter never reset -> replay-safe)
__device__ __forceinline__ void grid_sync(int ncta) {
    __syncthreads();
    if (threadIdx.x == 0) {
        __threadfence();
        unsigned ticket = atomicAdd(&g_bar, 1u);
        unsigned target = ((ticket / (unsigned)ncta) + 1u) * (unsigned)ncta;
        while (true) {
            unsigned v;
            asm volatile("ld.acquire.gpu.u32 %0, [%1];" : "=r"(v) : "l"(&g_bar));
            if (v >= target) break;
            __nanosleep(64);
        }
    }
    __syncthreads();
}

// ===================== fused persistent kernel =====================
__global__ void __launch_bounds__(512, 1) supcon_fused(
    const float* __restrict__ feats, const int* __restrict__ labels,
    float* __restrict__ out, int ncta
) {
    extern __shared__ char smem[];
    const int t = threadIdx.x, lane = t & 31, wid = t >> 5;
    const int bid = blockIdx.x;
    const int nwarp_tot = ncta * 16;
    const int gwarp = bid * 16 + wid;
    const uint32_t sbase = smem_u32(smem);
    const uint32_t mb = sbase + OFF_MBAR;
    float* red = reinterpret_cast<float*>(smem + OFF_RED);   // [4][128] floats

    // ---------------- phase 0: normalize + view-swap -> bf16 + fp8 ----------------
    if (bid == 0 && t == 0) g_sum = 0.f;
    for (int row = gwarp; row < NTOT; row += nwarp_tot) {
        int b = row & (BATCH - 1);
        int v = row >> 12;
        const float4* src = reinterpret_cast<const float4*>(feats + (size_t)(b * NVIEW + v) * DIM);
        float4 f[4];
        float ss = 0.f;
#pragma unroll
        for (int q = 0; q < 4; q++) {
            f[q] = src[lane + 32 * q];
            ss += f[q].x * f[q].x + f[q].y * f[q].y + f[q].z * f[q].z + f[q].w * f[q].w;
        }
#pragma unroll
        for (int o = 16; o; o >>= 1) ss += __shfl_xor_sync(0xffffffffu, ss, o);
        float sc = 1.0f / fmaxf(sqrtf(ss), 1e-8f);
        if (lane == 0) g_Z[row] = 0.f;
        uint2* dst = reinterpret_cast<uint2*>(g_A + (size_t)row * DIM);
        uint32_t* dst8 = reinterpret_cast<uint32_t*>(g_A8 + (size_t)row * DIM);
#pragma unroll
        for (int q = 0; q < 4; q++) {
            float x = f[q].x * sc, y = f[q].y * sc, z = f[q].z * sc, w = f[q].w * sc;
            __nv_bfloat162 p0 = __floats2bfloat162_rn(x, y);
            __nv_bfloat162 p1 = __floats2bfloat162_rn(z, w);
            uint2 pk;
            pk.x = *reinterpret_cast<uint32_t*>(&p0);
            pk.y = *reinterpret_cast<uint32_t*>(&p1);
            dst[lane + 32 * q] = pk;
            __nv_fp8x2_storage_t lo = __nv_cvt_float2_to_fp8x2(make_float2(x, y), __NV_SATFINITE, __NV_E4M3);
            __nv_fp8x2_storage_t hi = __nv_cvt_float2_to_fp8x2(make_float2(z, w), __NV_SATFINITE, __NV_E4M3);
            dst8[lane + 32 * q] = (uint32_t)lo | ((uint32_t)hi << 16);
        }
    }
    grid_sync(ncta);   // g_A / g_A8 / g_Z-zero complete

    // ---------------- phase 1: per-class feature sums + counts ----------------
    {
        int* list = reinterpret_cast<int*>(red);          // 160 ints
        int* pncnt = reinterpret_cast<int*>(red) + 160;
        for (int cls = bid; cls < NCLS; cls += ncta) {
            if (t < 32) {
                int n = 0;
                for (int base = 0; base < BATCH; base += 32) {
                    int lb = labels[base + lane];
                    unsigned bal = __ballot_sync(0xffffffffu, lb == cls);
                    if (lb == cls) {
                        int pos = n + __popc(bal & ((1u << lane) - 1));
                        if (pos < 160) list[pos] = base + lane;
                    }
                    n += __popc(bal);
                }
                if (lane == 0) { g_cnt[cls] = n; *pncnt = (n < 160) ? n : 160; }
            }
            __syncthreads();
            const int n = *pncnt;
            float acc = 0.f;
            for (int k = 0; k < n; k++) {
                int b = list[k];
                acc += __bfloat162float(g_A[(size_t)b * DIM + t])
                     + __bfloat162float(g_A[(size_t)(BATCH + b) * DIM + t]);
            }
            g_Ssum[cls * DIM + t] = acc;
            __syncthreads();
        }
    }
    // no sync needed: GEMM phase does not touch g_Ssum / g_cnt

    // ---------------- phase 2: fp8 GEMM upper triangle (identical to R10) ----------------
    {
        const int warp_m = wid >> 2, warp_n = wid & 3;      // 4 x 4 warps, 32x32 tiles
        const int g0 = (NTILES_TOTAL * bid) / ncta;
        const int g1 = (NTILES_TOTAL * (bid + 1)) / ncta;

        if (t == 0) { mbar_init(mb, 1); mbar_init(mb + 8, 1); }

        int ib0, c0;
        decode_tile(g0, ib0, c0);

        for (int f = t; f < 4096; f += 512) {
            int row = f >> 5, seg = f & 31;
            uint4 v = *reinterpret_cast<const uint4*>(g_A8 + (size_t)(ib0 * 128 + row) * DIM + seg * 16);
            *reinterpret_cast<uint4*>(smem + OFF_A + row * A_STRIDE + seg * 16) = v;
        }
        __syncthreads();   // A visible + mbars initialized

        {
            const int jb = (ib0 + c0) & 63;
            if (t == 0) mbar_expect(mb, 128 * 512);
            if (t < 128)
                bulk_cp(sbase + OFF_B + t * A_STRIDE, g_A8 + (size_t)jb * (128 * DIM) + t * 512, 512, mb);
        }

        const uint32_t abase = sbase + OFF_A + (warp_m * 32 + (lane & 15)) * A_STRIDE + (lane >> 4) * 16;
        const uint32_t bb_lane = (((lane & 7) + ((lane >> 4) & 1) * 8) + warp_n * 32) * A_STRIDE + ((lane >> 3) & 1) * 16;

        float acc[2][4][4];
#pragma unroll
        for (int m = 0; m < 2; m++)
#pragma unroll
            for (int n = 0; n < 4; n++)
#pragma unroll
                for (int r = 0; r < 4; r++) acc[m][n][r] = 0.f;
        float z[4] = {0.f, 0.f, 0.f, 0.f};
        int cur_ib = ib0;

        for (int g = g0; g < g1; g++) {
            const int jl = g - g0;
            const int buf = jl & 1;
            int ib, c;
            decode_tile(g, ib, c);
            __syncthreads();
            if (g + 1 < g1) {
                int ibn, cn;
                decode_tile(g + 1, ibn, cn);
                const int jb = (ibn + cn) & 63;
                const uint32_t mbn = mb + 8 * (buf ^ 1);
                if (t == 0) mbar_expect(mbn, 128 * 512);
                if (t < 128)
                    bulk_cp(sbase + OFF_B + (buf ^ 1) * TILE_BYTES + t * A_STRIDE,
                            g_A8 + (size_t)jb * (128 * DIM) + t * 512, 512, mbn);
            }
            if (ib != cur_ib) {
#pragma unroll
                for (int q = 0; q < 4; q++) {
                    z[q] += __shfl_xor_sync(0xffffffffu, z[q], 1);
                    z[q] += __shfl_xor_sync(0xffffffffu, z[q], 2);
                }
                if ((lane & 3) == 0) {
                    int g4 = lane >> 2;
#pragma unroll
                    for (int m = 0; m < 2; m++)
#pragma unroll
                        for (int h = 0; h < 2; h++)
                            red[warp_n * 128 + warp_m * 32 + m * 16 + h * 8 + g4] = z[2 * m + h];
                }
                __syncthreads();
                if (t < 128)
                    atomicAdd(&g_Z[cur_ib * 128 + t],
                              (red[t] + red[128 + t] + red[256 + t] + red[384 + t]) * ESCALE);
                z[0] = z[1] = z[2] = z[3] = 0.f;
                for (int f = t; f < 4096; f += 512) {
                    int row = f >> 5, seg = f & 31;
                    uint4 v = *reinterpret_cast<const uint4*>(g_A8 + (size_t)(ib * 128 + row) * DIM + seg * 16);
                    *reinterpret_cast<uint4*>(smem + OFF_A + row * A_STRIDE + seg * 16) = v;
                }
                cur_ib = ib;
                __syncthreads();
            }
            mbar_wait(mb + 8 * buf, (jl >> 1) & 1);

            const uint32_t bb = sbase + OFF_B + buf * TILE_BYTES + bb_lane;
#pragma unroll
            for (int ks = 0; ks < 16; ks++) {
                const int koff = ks * 32;
                uint32_t a[2][4];
                ldm4(a[0], abase + koff);
                ldm4(a[1], abase + 16 * A_STRIDE + koff);
                uint32_t b[4][2];
#pragma unroll
                for (int p = 0; p < 2; p++) {
                    uint32_t r4[4];
                    ldm4(r4, bb + p * (16 * A_STRIDE) + koff);
                    b[2 * p][0] = r4[0]; b[2 * p][1] = r4[1];
                    b[2 * p + 1][0] = r4[2]; b[2 * p + 1][1] = r4[3];
                }
#pragma unroll
                for (int m = 0; m < 2; m++)
#pragma unroll
                    for (int n = 0; n < 4; n++) qmma(acc[m][n], a[m], b[n]);
            }

            {
                const int jblk = (ib + c) & 63;
                const bool dg = (c == 0);
                uint32_t zh[4] = {0, 0, 0, 0};
                uint32_t csh[4] = {0, 0, 0, 0};
#pragma unroll
                for (int m = 0; m < 2; m++)
#pragma unroll
                    for (int n = 0; n < 4; n++)
#pragma unroll
                        for (int h = 0; h < 2; h++) {
                            float x0 = acc[m][n][2 * h]     * C_EXP - EBIAS;
                            float x1 = acc[m][n][2 * h + 1] * C_EXP - EBIAS;
                            if (dg) {
                                int rl = warp_m * 32 + m * 16 + h * 8 + (lane >> 2);
                                int cl0 = warp_n * 32 + n * 8 + (lane & 3) * 2;
                                if (rl == cl0)     x0 = -60.f;
                                if (rl == cl0 + 1) x1 = -60.f;
                            }
                            uint32_t e2 = ex2_h2(pack_h2(x0, x1));
                            zh[2 * m + h] = hadd2(zh[2 * m + h], e2);
                            csh[n] = hadd2(csh[n], e2);
                            acc[m][n][2 * h] = 0.f; acc[m][n][2 * h + 1] = 0.f;
                        }
#pragma unroll
                for (int q = 0; q < 4; q++) {
                    float2 f = h2_to_f2(zh[q]);
                    z[q] += f.x + f.y;
                }
                if (!dg) {
#pragma unroll
                    for (int n = 0; n < 4; n++) {
                        uint32_t v = csh[n];
                        v = hadd2(v, __shfl_xor_sync(0xffffffffu, v, 4));
                        v = hadd2(v, __shfl_xor_sync(0xffffffffu, v, 8));
                        v = hadd2(v, __shfl_xor_sync(0xffffffffu, v, 16));
                        csh[n] = v;
                    }
                    if (lane < 4) {
                        float* zj = &g_Z[jblk * 128 + warp_n * 32 + lane * 2];
#pragma unroll
                        for (int n = 0; n < 4; n++) {
                            float2 f = h2_to_f2(csh[n]);
                            atomicAdd(&zj[n * 8 + 0], f.x * ESCALE);
                            atomicAdd(&zj[n * 8 + 1], f.y * ESCALE);
                        }
                    }
                }
            }
        }

        // final flush of row sums for cur_ib
#pragma unroll
        for (int q = 0; q < 4; q++) {
            z[q] += __shfl_xor_sync(0xffffffffu, z[q], 1);
            z[q] += __shfl_xor_sync(0xffffffffu, z[q], 2);
        }
        __syncthreads();
        if ((lane & 3) == 0) {
            int g4 = lane >> 2;
#pragma unroll
            for (int m = 0; m < 2; m++)
#pragma unroll
                for (int h = 0; h < 2; h++)
                    red[warp_n * 128 + warp_m * 32 + m * 16 + h * 8 + g4] = z[2 * m + h];
        }
        __syncthreads();
        if (t < 128)
            atomicAdd(&g_Z[cur_ib * 128 + t],
                      (red[t] + red[128 + t] + red[256 + t] + red[384 + t]) * ESCALE);
    }
    grid_sync(ncta);   // g_Z complete (g_Ssum/g_cnt completed before this sync too)

    // ---------------- phase 3: per-row loss ----------------
    {
        float lsum = 0.f;
        for (int row = gwarp; row < NTOT; row += nwarp_tot) {
            const int b = row & (BATCH - 1);
            const int cls = labels[b];
            const uint2* arow = reinterpret_cast<const uint2*>(g_A) + (size_t)row * 128;
            const float4* srow = reinterpret_cast<const float4*>(g_Ssum) + (size_t)cls * 128;
            float dot = 0.f, self = 0.f;
#pragma unroll
            for (int q = 0; q < 4; q++) {
                uint2 u = arow[lane + 32 * q];
                float4 s = srow[lane + 32 * q];
                float2 a0 = __bfloat1622float2(*reinterpret_cast<const __nv_bfloat162*>(&u.x));
                float2 a1 = __bfloat1622float2(*reinterpret_cast<const __nv_bfloat162*>(&u.y));
                dot  += a0.x * s.x + a0.y * s.y + a1.x * s.z + a1.y * s.w;
                self += a0.x * a0.x + a0.y * a0.y + a1.x * a1.x + a1.y * a1.y;
            }
#pragma unroll
            for (int o = 16; o; o >>= 1) {
                dot  += __shfl_xor_sync(0xffffffffu, dot, o);
                self += __shfl_xor_sync(0xffffffffu, self, o);
            }
            if (lane == 0) {
                float C = 2.0f * (float)g_cnt[cls] - 1.0f;
                float Z = g_Z[row];
                float S = (dot - self) * INV_T;
                lsum += (S - C * logf(Z + 1e-8f)) / (C + 1e-8f);
            }
        }
        __syncthreads();   // red reuse safe
        if (lane == 0) red[wid] = lsum;
        __syncthreads();
        if (t == 0) {
            float bs = 0.f;
#pragma unroll
            for (int w = 0; w < 16; w++) bs += red[w];
            atomicAdd(&g_sum, bs);
        }
    }
    grid_sync(ncta);   // g_sum complete

    if (bid == 0 && t == 0) out[0] = -g_sum / (float)NTOT;
}

// ------------------------- launch -------------------------
extern "C" void kernel_launch(void* const* d_in, const int* in_sizes, int n_in,
                              void* d_out, int out_size) {
    const float* feats = (const float*)d_in[0];
    const int* labels = (const int*)d_in[1];
    (void)in_sizes; (void)n_in; (void)out_size;

    int nsm = 0;
    cudaDeviceGetAttribute(&nsm, cudaDevAttrMultiProcessorCount, 0);
    int ncta = (nsm > 0) ? nsm : 128;
    if (ncta > NTILES_TOTAL) ncta = NTILES_TOTAL;

    cudaFuncSetAttribute(supcon_fused, cudaFuncAttributeMaxDynamicSharedMemorySize, SMEM_TOTAL);
    supcon_fused<<<ncta, 512, SMEM_TOTAL>>>(feats, labels, (float*)d_out, ncta);
}

// round 12
// speedup vs baseline: 2.0170x; 2.0170x over previous
#include <cuda_runtime.h>
#include <cuda_bf16.h>
#include <cuda_fp8.h>
#include <cstdint>

#define BATCH 4096
#define NVIEW 2
#define DIM   512
#define NTOT  8192
#define NCLS  1000

#define C_EXP  20.60992915555662f   // log2(e)/0.07
#define INV_T  14.285714285714286f  // 1/0.07
#define EBIAS  10.0f
#define ESCALE 1024.0f              // 2^EBIAS

#define NTILES_TOTAL 2080
#define NCTA 148

// ---------------- smem layout (bytes) ----------------
#define A_STRIDE   528                 // 512 fp8 + 16 pad per row -> conflict-free ldmatrix
#define TILE_BYTES (128 * A_STRIDE)    // 67584
#define OFF_A      0
#define OFF_B      TILE_BYTES          // two full-K B stages
#define OFF_RED    (OFF_B + 2 * TILE_BYTES)   // 202752
#define OFF_MBAR   (OFF_RED + 4 * 128 * 4)    // 204800
#define SMEM_TOTAL (OFF_MBAR + 16)            // 204816

// ---------------- scratch ----------------
__device__ __align__(16) __nv_bfloat16 g_A[(size_t)NTOT * DIM];
__device__ __align__(16) uint8_t       g_A8[(size_t)NTOT * DIM];
__device__ __align__(16) float         g_Ssum[NCLS * DIM];
__device__ float g_Z[NTOT];
__device__ float g_sum;
__device__ int   g_cnt[NCLS];
__device__ unsigned g_done;

// ---------------- PTX helpers ----------------
__device__ __forceinline__ void ldm4(uint32_t r[4], uint32_t addr) {
    asm volatile("ldmatrix.sync.aligned.m8n8.x4.shared.b16 {%0,%1,%2,%3}, [%4];"
        : "=r"(r[0]), "=r"(r[1]), "=r"(r[2]), "=r"(r[3]) : "r"(addr));
}
__device__ __forceinline__ void qmma(float c[4], const uint32_t a[4], const uint32_t b[2]) {
    asm volatile("mma.sync.aligned.m16n8k32.row.col.f32.e4m3.e4m3.f32 "
        "{%0,%1,%2,%3}, {%4,%5,%6,%7}, {%8,%9}, {%0,%1,%2,%3};"
        : "+f"(c[0]), "+f"(c[1]), "+f"(c[2]), "+f"(c[3])
        : "r"(a[0]), "r"(a[1]), "r"(a[2]), "r"(a[3]), "r"(b[0]), "r"(b[1]));
}
__device__ __forceinline__ uint32_t smem_u32(const void* p) {
    uint32_t a;
    asm("{ .reg .u64 t; cvta.to.shared.u64 t, %1; cvt.u32.u64 %0, t; }" : "=r"(a) : "l"(p));
    return a;
}
__device__ __forceinline__ void bulk_cp(uint32_t dst, const void* src, uint32_t bytes, uint32_t mbar) {
    asm volatile("cp.async.bulk.shared::cta.global.mbarrier::complete_tx::bytes [%0], [%1], %2, [%3];"
        :: "r"(dst), "l"(src), "r"(bytes), "r"(mbar) : "memory");
}
__device__ __forceinline__ void mbar_init(uint32_t mbar, uint32_t cnt) {
    asm volatile("mbarrier.init.shared.b64 [%0], %1;" :: "r"(mbar), "r"(cnt) : "memory");
}
__device__ __forceinline__ void mbar_expect(uint32_t mbar, uint32_t bytes) {
    asm volatile("mbarrier.arrive.expect_tx.shared.b64 _, [%0], %1;" :: "r"(mbar), "r"(bytes) : "memory");
}
__device__ __forceinline__ void mbar_wait(uint32_t mbar, uint32_t parity) {
    uint32_t done;
    asm volatile("{ .reg .pred p; mbarrier.try_wait.parity.acquire.cta.shared::cta.b64 p, [%1], %2; selp.b32 %0, 1, 0, p; }"
        : "=r"(done) : "r"(mbar), "r"(parity) : "memory");
    if (!done) {
        asm volatile("{ .reg .pred P1;\n"
            "W_%=: mbarrier.try_wait.parity.acquire.cta.shared::cta.b64 P1, [%0], %1, 0x989680;\n"
            "@P1 bra.uni D_%=;\n bra.uni W_%=;\n D_%=: }"
            :: "r"(mbar), "r"(parity) : "memory");
    }
}
__device__ __forceinline__ uint32_t pack_h2(float lo, float hi) {
    uint32_t h;
    asm("cvt.rn.f16x2.f32 %0, %1, %2;" : "=r"(h) : "f"(hi), "f"(lo));
    return h;
}
__device__ __forceinline__ uint32_t ex2_h2(uint32_t x) {
    uint32_t e;
    asm("ex2.approx.f16x2 %0, %1;" : "=r"(e) : "r"(x));
    return e;
}
__device__ __forceinline__ uint32_t hadd2(uint32_t a, uint32_t b) {
    uint32_t d;
    asm("add.rn.f16x2 %0, %1, %2;" : "=r"(d) : "r"(a), "r"(b));
    return d;
}
__device__ __forceinline__ float2 h2_to_f2(uint32_t h) {
    float lo, hi;
    asm("{ .reg .f16 l, hh; mov.b32 {l, hh}, %2; cvt.f32.f16 %0, l; cvt.f32.f16 %1, hh; }"
        : "=f"(lo), "=f"(hi) : "r"(h));
    return make_float2(lo, hi);
}
// flattened upper-triangle tile list: iblk<32 -> c in [0,33), else c in [0,32)
__device__ __forceinline__ void decode_tile(int g, int& ib, int& c) {
    if (g < 1056) { ib = g / 33; c = g - ib * 33; }
    else { int h = g - 1056; ib = 32 + (h >> 5); c = h & 31; }
}

// ------------------------- kernel 1: normalize + view-swap + class-sum scatter -------------------------
__global__ void norm_kernel(const float* __restrict__ feats, const int* __restrict__ labels) {
    int warp = threadIdx.x >> 5, lane = threadIdx.x & 31;
    int row  = blockIdx.x * 8 + warp;
    int b = row & (BATCH - 1);
    int v = row >> 12;
    const int cls = labels[b];
    const float4* src = reinterpret_cast<const float4*>(feats + (size_t)(b * NVIEW + v) * DIM);
    float4 f[4];
    float ss = 0.f;
#pragma unroll
    for (int q = 0; q < 4; q++) {
        f[q] = src[lane + 32 * q];
        ss += f[q].x * f[q].x + f[q].y * f[q].y + f[q].z * f[q].z + f[q].w * f[q].w;
    }
#pragma unroll
    for (int o = 16; o; o >>= 1) ss += __shfl_xor_sync(0xffffffffu, ss, o);
    float sc = 1.0f / fmaxf(sqrtf(ss), 1e-8f);
    if (lane == 0) {
        g_Z[row] = 0.f;
        if (v == 0) atomicAdd(&g_cnt[cls], 1);
    }
    uint2* dst = reinterpret_cast<uint2*>(g_A + (size_t)row * DIM);
    uint32_t* dst8 = reinterpret_cast<uint32_t*>(g_A8 + (size_t)row * DIM);
    float* sdst = g_Ssum + (size_t)cls * DIM;
#pragma unroll
    for (int q = 0; q < 4; q++) {
        float x = f[q].x * sc, y = f[q].y * sc, z = f[q].z * sc, w = f[q].w * sc;
        __nv_bfloat162 p0 = __floats2bfloat162_rn(x, y);
        __nv_bfloat162 p1 = __floats2bfloat162_rn(z, w);
        uint2 pk;
        pk.x = *reinterpret_cast<uint32_t*>(&p0);
        pk.y = *reinterpret_cast<uint32_t*>(&p1);
        dst[lane + 32 * q] = pk;
        __nv_fp8x2_storage_t lo = __nv_cvt_float2_to_fp8x2(make_float2(x, y), __NV_SATFINITE, __NV_E4M3);
        __nv_fp8x2_storage_t hi = __nv_cvt_float2_to_fp8x2(make_float2(z, w), __NV_SATFINITE, __NV_E4M3);
        dst8[lane + 32 * q] = (uint32_t)lo | ((uint32_t)hi << 16);
        int d0 = (lane + 32 * q) * 4;
        atomicAdd(&sdst[d0 + 0], x);
        atomicAdd(&sdst[d0 + 1], y);
        atomicAdd(&sdst[d0 + 2], z);
        atomicAdd(&sdst[d0 + 3], w);
    }
}

// ------------------------- kernel 2: fp8 GEMM upper triangle, flat 148-CTA schedule (R10, verified) -------------------------
__global__ void __launch_bounds__(512, 1) supcon_main() {
    extern __shared__ char smem[];
    const int t = threadIdx.x, lane = t & 31, wid = t >> 5;
    const int warp_m = wid >> 2, warp_n = wid & 3;      // 4 x 4 warps, 32x32 tiles
    const int g0 = (NTILES_TOTAL * blockIdx.x) / NCTA;
    const int g1 = (NTILES_TOTAL * (blockIdx.x + 1)) / NCTA;
    const uint32_t sbase = smem_u32(smem);
    const uint32_t mb = sbase + OFF_MBAR;
    float* red = reinterpret_cast<float*>(smem + OFF_RED);   // [4][128]

    if (t == 0) { mbar_init(mb, 1); mbar_init(mb + 8, 1); }

    int ib0, c0;
    decode_tile(g0, ib0, c0);

    // load A tile for first iblk
    for (int f = t; f < 4096; f += 512) {
        int row = f >> 5, seg = f & 31;
        uint4 v = *reinterpret_cast<const uint4*>(g_A8 + (size_t)(ib0 * 128 + row) * DIM + seg * 16);
        *reinterpret_cast<uint4*>(smem + OFF_A + row * A_STRIDE + seg * 16) = v;
    }
    __syncthreads();   // A visible + mbars initialized

    // prologue: bulk-copy B tile of g0 into buf 0
    {
        const int jb = (ib0 + c0) & 63;
        if (t == 0) mbar_expect(mb, 128 * 512);
        if (t < 128)
            bulk_cp(sbase + OFF_B + t * A_STRIDE, g_A8 + (size_t)jb * (128 * DIM) + t * 512, 512, mb);
    }

    const uint32_t abase = sbase + OFF_A + (warp_m * 32 + (lane & 15)) * A_STRIDE + (lane >> 4) * 16;
    const uint32_t bb_lane = (((lane & 7) + ((lane >> 4) & 1) * 8) + warp_n * 32) * A_STRIDE + ((lane >> 3) & 1) * 16;

    float acc[2][4][4];
#pragma unroll
    for (int m = 0; m < 2; m++)
#pragma unroll
        for (int n = 0; n < 4; n++)
#pragma unroll
            for (int r = 0; r < 4; r++) acc[m][n][r] = 0.f;
    float z[4] = {0.f, 0.f, 0.f, 0.f};
    int cur_ib = ib0;

    for (int g = g0; g < g1; g++) {
        const int jl = g - g0;
        const int buf = jl & 1;
        int ib, c;
        decode_tile(g, ib, c);
        __syncthreads();                 // all warps done with buf^1 (tile g-1) and with old A
        if (g + 1 < g1) {
            int ibn, cn;
            decode_tile(g + 1, ibn, cn);
            const int jb = (ibn + cn) & 63;
            const uint32_t mbn = mb + 8 * (buf ^ 1);
            if (t == 0) mbar_expect(mbn, 128 * 512);
            if (t < 128)
                bulk_cp(sbase + OFF_B + (buf ^ 1) * TILE_BYTES + t * A_STRIDE,
                        g_A8 + (size_t)jb * (128 * DIM) + t * 512, 512, mbn);
        }
        if (ib != cur_ib) {
            // flush row sums for cur_ib
#pragma unroll
            for (int q = 0; q < 4; q++) {
                z[q] += __shfl_xor_sync(0xffffffffu, z[q], 1);
                z[q] += __shfl_xor_sync(0xffffffffu, z[q], 2);
            }
            if ((lane & 3) == 0) {
                int g4 = lane >> 2;
#pragma unroll
                for (int m = 0; m < 2; m++)
#pragma unroll
                    for (int h = 0; h < 2; h++)
                        red[warp_n * 128 + warp_m * 32 + m * 16 + h * 8 + g4] = z[2 * m + h];
            }
            __syncthreads();
            if (t < 128)
                atomicAdd(&g_Z[cur_ib * 128 + t],
                          (red[t] + red[128 + t] + red[256 + t] + red[384 + t]) * ESCALE);
            z[0] = z[1] = z[2] = z[3] = 0.f;
            // reload A for new iblk
            for (int f = t; f < 4096; f += 512) {
                int row = f >> 5, seg = f & 31;
                uint4 v = *reinterpret_cast<const uint4*>(g_A8 + (size_t)(ib * 128 + row) * DIM + seg * 16);
                *reinterpret_cast<uint4*>(smem + OFF_A + row * A_STRIDE + seg * 16) = v;
            }
            cur_ib = ib;
            __syncthreads();
        }
        mbar_wait(mb + 8 * buf, (jl >> 1) & 1);

        const uint32_t bb = sbase + OFF_B + buf * TILE_BYTES + bb_lane;
#pragma unroll
        for (int ks = 0; ks < 16; ks++) {
            const int koff = ks * 32;
            uint32_t a[2][4];
            ldm4(a[0], abase + koff);
            ldm4(a[1], abase + 16 * A_STRIDE + koff);
            uint32_t b[4][2];
#pragma unroll
            for (int p = 0; p < 2; p++) {
                uint32_t r4[4];
                ldm4(r4, bb + p * (16 * A_STRIDE) + koff);
                b[2 * p][0] = r4[0]; b[2 * p][1] = r4[1];
                b[2 * p + 1][0] = r4[2]; b[2 * p + 1][1] = r4[3];
            }
#pragma unroll
            for (int m = 0; m < 2; m++)
#pragma unroll
                for (int n = 0; n < 4; n++) qmma(acc[m][n], a[m], b[n]);
        }

        // ---- epilogue: f16x2 exp, row sums + REDG column sums ----
        {
            const int jblk = (ib + c) & 63;
            const bool dg = (c == 0);
            uint32_t zh[4] = {0, 0, 0, 0};
            uint32_t csh[4] = {0, 0, 0, 0};
#pragma unroll
            for (int m = 0; m < 2; m++)
#pragma unroll
                for (int n = 0; n < 4; n++)
#pragma unroll
                    for (int h = 0; h < 2; h++) {
                        float x0 = acc[m][n][2 * h]     * C_EXP - EBIAS;
                        float x1 = acc[m][n][2 * h + 1] * C_EXP - EBIAS;
                        if (dg) {
                            int rl = warp_m * 32 + m * 16 + h * 8 + (lane >> 2);
                            int cl0 = warp_n * 32 + n * 8 + (lane & 3) * 2;
                            if (rl == cl0)     x0 = -60.f;
                            if (rl == cl0 + 1) x1 = -60.f;
                        }
                        uint32_t e2 = ex2_h2(pack_h2(x0, x1));
                        zh[2 * m + h] = hadd2(zh[2 * m + h], e2);
                        csh[n] = hadd2(csh[n], e2);
                        acc[m][n][2 * h] = 0.f; acc[m][n][2 * h + 1] = 0.f;
                    }
#pragma unroll
            for (int q = 0; q < 4; q++) {
                float2 f = h2_to_f2(zh[q]);
                z[q] += f.x + f.y;
            }
            if (!dg) {
#pragma unroll
                for (int n = 0; n < 4; n++) {
                    uint32_t v = csh[n];
                    v = hadd2(v, __shfl_xor_sync(0xffffffffu, v, 4));
                    v = hadd2(v, __shfl_xor_sync(0xffffffffu, v, 8));
                    v = hadd2(v, __shfl_xor_sync(0xffffffffu, v, 16));
                    csh[n] = v;
                }
                if (lane < 4) {
                    float* zj = &g_Z[jblk * 128 + warp_n * 32 + lane * 2];
#pragma unroll
                    for (int n = 0; n < 4; n++) {
                        float2 f = h2_to_f2(csh[n]);
                        atomicAdd(&zj[n * 8 + 0], f.x * ESCALE);
                        atomicAdd(&zj[n * 8 + 1], f.y * ESCALE);
                    }
                }
            }
        }
    }

    // final flush of row sums for cur_ib
#pragma unroll
    for (int q = 0; q < 4; q++) {
        z[q] += __shfl_xor_sync(0xffffffffu, z[q], 1);
        z[q] += __shfl_xor_sync(0xffffffffu, z[q], 2);
    }
    __syncthreads();
    if ((lane & 3) == 0) {
        int g4 = lane >> 2;
#pragma unroll
        for (int m = 0; m < 2; m++)
#pragma unroll
            for (int h = 0; h < 2; h++)
                red[warp_n * 128 + warp_m * 32 + m * 16 + h * 8 + g4] = z[2 * m + h];
    }
    __syncthreads();
    if (t < 128)
        atomicAdd(&g_Z[cur_ib * 128 + t],
                  (red[t] + red[128 + t] + red[256 + t] + red[384 + t]) * ESCALE);
}

// ------------------------- kernel 3: per-row loss + last-block final write -------------------------
__global__ void finalize1(const int* __restrict__ labels, float* __restrict__ out) {
    __shared__ float wsum[8];
    const int t = threadIdx.x, lane = t & 31, wid = t >> 5;
    const int row = blockIdx.x * 8 + wid;
    const int b = row & (BATCH - 1);
    const int cls = labels[b];
    const uint2* arow = reinterpret_cast<const uint2*>(g_A) + (size_t)row * 128;
    const float4* srow = reinterpret_cast<const float4*>(g_Ssum) + (size_t)cls * 128;
    float dot = 0.f, self = 0.f;
#pragma unroll
    for (int q = 0; q < 4; q++) {
        uint2 u = arow[lane + 32 * q];
        float4 s = srow[lane + 32 * q];
        float2 a0 = __bfloat1622float2(*reinterpret_cast<const __nv_bfloat162*>(&u.x));
        float2 a1 = __bfloat1622float2(*reinterpret_cast<const __nv_bfloat162*>(&u.y));
        dot  += a0.x * s.x + a0.y * s.y + a1.x * s.z + a1.y * s.w;
        self += a0.x * a0.x + a0.y * a0.y + a1.x * a1.x + a1.y * a1.y;
    }
#pragma unroll
    for (int o = 16; o; o >>= 1) {
        dot  += __shfl_xor_sync(0xffffffffu, dot, o);
        self += __shfl_xor_sync(0xffffffffu, self, o);
    }
    if (lane == 0) {
        float C = 2.0f * (float)g_cnt[cls] - 1.0f;
        float Z = g_Z[row];
        float S = (dot - self) * INV_T;
        wsum[wid] = (S - C * logf(Z + 1e-8f)) / (C + 1e-8f);
    }
    __syncthreads();
    if (t == 0) {
        float bs = 0.f;
#pragma unroll
        for (int w = 0; w < 8; w++) bs += wsum[w];
        atomicAdd(&g_sum, bs);
        __threadfence();
        unsigned tk = atomicAdd(&g_done, 1u);
        if (tk == gridDim.x - 1) {   // all blocks' g_sum adds visible
            float s;
            asm volatile("ld.acquire.gpu.f32 %0, [%1];" : "=f"(s) : "l"(&g_sum));
            out[0] = -s / (float)NTOT;
        }
    }
}

// ------------------------- launch -------------------------
extern "C" void kernel_launch(void* const* d_in, const int* in_sizes, int n_in,
                              void* d_out, int out_size) {
    const float* feats = (const float*)d_in[0];
    const int* labels = (const int*)d_in[1];
    (void)in_sizes; (void)n_in; (void)out_size;

    void* p_ssum = nullptr; void* p_cnt = nullptr; void* p_sum = nullptr; void* p_done = nullptr;
    cudaGetSymbolAddress(&p_ssum, g_Ssum);
    cudaGetSymbolAddress(&p_cnt, g_cnt);
    cudaGetSymbolAddress(&p_sum, g_sum);
    cudaGetSymbolAddress(&p_done, g_done);
    cudaMemsetAsync(p_ssum, 0, (size_t)NCLS * DIM * sizeof(float));
    cudaMemsetAsync(p_cnt, 0, NCLS * sizeof(int));
    cudaMemsetAsync(p_sum, 0, sizeof(float));
    cudaMemsetAsync(p_done, 0, sizeof(unsigned));

    cudaFuncSetAttribute(supcon_main, cudaFuncAttributeMaxDynamicSharedMemorySize, SMEM_TOTAL);

    norm_kernel<<<NTOT / 8, 256>>>(feats, labels);
    supcon_main<<<NCTA, 512, SMEM_TOTAL>>>();
    finalize1<<<NTOT / 8, 256>>>(labels, (float*)d_out);
}

// round 13
// speedup vs baseline: 2.1398x; 1.0609x over previous
#include <cuda_runtime.h>
#include <cuda_bf16.h>
#include <cuda_fp8.h>
#include <cstdint>

#define BATCH 4096
#define NVIEW 2
#define DIM   512
#define NTOT  8192
#define NCLS  1000

#define C_EXP  20.60992915555662f   // log2(e)/0.07
#define INV_T  14.285714285714286f  // 1/0.07
#define EBIAS  10.0f
#define ESCALE 1024.0f              // 2^EBIAS

#define NTILES_TOTAL 2080
#define NCTA 148

// ---------------- smem layout (bytes) ----------------
#define A_STRIDE   528                 // 512 fp8 + 16 pad per row -> conflict-free ldmatrix
#define TILE_BYTES (128 * A_STRIDE)    // 67584
#define OFF_A      0
#define OFF_B      TILE_BYTES          // two full-K B stages
#define OFF_RED    (OFF_B + 2 * TILE_BYTES)   // 202752
#define OFF_MBAR   (OFF_RED + 4 * 128 * 4)    // 204800
#define SMEM_TOTAL (OFF_MBAR + 16)            // 204816

// ---------------- scratch ----------------
__device__ __align__(16) __nv_bfloat16 g_A[(size_t)NTOT * DIM];
__device__ __align__(16) uint8_t       g_A8[(size_t)NTOT * DIM];
__device__ __align__(16) float         g_Ssum[NCLS * DIM];
__device__ float g_Z[NTOT];
__device__ float g_sum;
__device__ int   g_cnt[NCLS];
__device__ unsigned g_done;

// ---------------- PTX helpers ----------------
__device__ __forceinline__ void ldm4(uint32_t r[4], uint32_t addr) {
    asm volatile("ldmatrix.sync.aligned.m8n8.x4.shared.b16 {%0,%1,%2,%3}, [%4];"
        : "=r"(r[0]), "=r"(r[1]), "=r"(r[2]), "=r"(r[3]) : "r"(addr));
}
__device__ __forceinline__ void qmma(float c[4], const uint32_t a[4], const uint32_t b[2]) {
    asm volatile("mma.sync.aligned.m16n8k32.row.col.f32.e4m3.e4m3.f32 "
        "{%0,%1,%2,%3}, {%4,%5,%6,%7}, {%8,%9}, {%0,%1,%2,%3};"
        : "+f"(c[0]), "+f"(c[1]), "+f"(c[2]), "+f"(c[3])
        : "r"(a[0]), "r"(a[1]), "r"(a[2]), "r"(a[3]), "r"(b[0]), "r"(b[1]));
}
__device__ __forceinline__ uint32_t smem_u32(const void* p) {
    uint32_t a;
    asm("{ .reg .u64 t; cvta.to.shared.u64 t, %1; cvt.u32.u64 %0, t; }" : "=r"(a) : "l"(p));
    return a;
}
__device__ __forceinline__ void bulk_cp(uint32_t dst, const void* src, uint32_t bytes, uint32_t mbar) {
    asm volatile("cp.async.bulk.shared::cta.global.mbarrier::complete_tx::bytes [%0], [%1], %2, [%3];"
        :: "r"(dst), "l"(src), "r"(bytes), "r"(mbar) : "memory");
}
__device__ __forceinline__ void bulk_red_add_f32(void* gdst, uint32_t ssrc, uint32_t bytes) {
    asm volatile("cp.reduce.async.bulk.global.shared::cta.bulk_group.add.f32 [%0], [%1], %2;"
        :: "l"(gdst), "r"(ssrc), "r"(bytes) : "memory");
}
__device__ __forceinline__ void bulk_commit() {
    asm volatile("cp.async.bulk.commit_group;" ::: "memory");
}
__device__ __forceinline__ void bulk_wait0() {
    asm volatile("cp.async.bulk.wait_group 0;" ::: "memory");
}
__device__ __forceinline__ void mbar_init(uint32_t mbar, uint32_t cnt) {
    asm volatile("mbarrier.init.shared.b64 [%0], %1;" :: "r"(mbar), "r"(cnt) : "memory");
}
__device__ __forceinline__ void mbar_expect(uint32_t mbar, uint32_t bytes) {
    asm volatile("mbarrier.arrive.expect_tx.shared.b64 _, [%0], %1;" :: "r"(mbar), "r"(bytes) : "memory");
}
__device__ __forceinline__ void mbar_wait(uint32_t mbar, uint32_t parity) {
    uint32_t done;
    asm volatile("{ .reg .pred p; mbarrier.try_wait.parity.acquire.cta.shared::cta.b64 p, [%1], %2; selp.b32 %0, 1, 0, p; }"
        : "=r"(done) : "r"(mbar), "r"(parity) : "memory");
    if (!done) {
        asm volatile("{ .reg .pred P1;\n"
            "W_%=: mbarrier.try_wait.parity.acquire.cta.shared::cta.b64 P1, [%0], %1, 0x989680;\n"
            "@P1 bra.uni D_%=;\n bra.uni W_%=;\n D_%=: }"
            :: "r"(mbar), "r"(parity) : "memory");
    }
}
__device__ __forceinline__ uint32_t pack_h2(float lo, float hi) {
    uint32_t h;
    asm("cvt.rn.f16x2.f32 %0, %1, %2;" : "=r"(h) : "f"(hi), "f"(lo));
    return h;
}
__device__ __forceinline__ uint32_t ex2_h2(uint32_t x) {
    uint32_t e;
    asm("ex2.approx.f16x2 %0, %1;" : "=r"(e) : "r"(x));
    return e;
}
__device__ __forceinline__ uint32_t hadd2(uint32_t a, uint32_t b) {
    uint32_t d;
    asm("add.rn.f16x2 %0, %1, %2;" : "=r"(d) : "r"(a), "r"(b));
    return d;
}
__device__ __forceinline__ float2 h2_to_f2(uint32_t h) {
    float lo, hi;
    asm("{ .reg .f16 l, hh; mov.b32 {l, hh}, %2; cvt.f32.f16 %0, l; cvt.f32.f16 %1, hh; }"
        : "=f"(lo), "=f"(hi) : "r"(h));
    return make_float2(lo, hi);
}
// flattened upper-triangle tile list: iblk<32 -> c in [0,33), else c in [0,32)
__device__ __forceinline__ void decode_tile(int g, int& ib, int& c) {
    if (g < 1056) { ib = g / 33; c = g - ib * 33; }
    else { int h = g - 1056; ib = 32 + (h >> 5); c = h & 31; }
}

// ------------------------- kernel 1: normalize + view-swap + bulk-reduce class sums -------------------------
__global__ void norm_kernel(const float* __restrict__ feats, const int* __restrict__ labels) {
    __shared__ float stage[8][DIM];
    int warp = threadIdx.x >> 5, lane = threadIdx.x & 31;
    int row  = blockIdx.x * 8 + warp;
    int b = row & (BATCH - 1);
    int v = row >> 12;
    const int cls = labels[b];
    const float4* src = reinterpret_cast<const float4*>(feats + (size_t)(b * NVIEW + v) * DIM);
    float4 f[4];
    float ss = 0.f;
#pragma unroll
    for (int q = 0; q < 4; q++) {
        f[q] = src[lane + 32 * q];
        ss += f[q].x * f[q].x + f[q].y * f[q].y + f[q].z * f[q].z + f[q].w * f[q].w;
    }
#pragma unroll
    for (int o = 16; o; o >>= 1) ss += __shfl_xor_sync(0xffffffffu, ss, o);
    float sc = 1.0f / fmaxf(sqrtf(ss), 1e-8f);
    if (lane == 0) {
        g_Z[row] = 0.f;
        if (v == 0) atomicAdd(&g_cnt[cls], 1);
    }
    uint2* dst = reinterpret_cast<uint2*>(g_A + (size_t)row * DIM);
    uint32_t* dst8 = reinterpret_cast<uint32_t*>(g_A8 + (size_t)row * DIM);
    float4* srow = reinterpret_cast<float4*>(stage[warp]);
#pragma unroll
    for (int q = 0; q < 4; q++) {
        float x = f[q].x * sc, y = f[q].y * sc, z = f[q].z * sc, w = f[q].w * sc;
        __nv_bfloat162 p0 = __floats2bfloat162_rn(x, y);
        __nv_bfloat162 p1 = __floats2bfloat162_rn(z, w);
        uint2 pk;
        pk.x = *reinterpret_cast<uint32_t*>(&p0);
        pk.y = *reinterpret_cast<uint32_t*>(&p1);
        dst[lane + 32 * q] = pk;
        __nv_fp8x2_storage_t lo = __nv_cvt_float2_to_fp8x2(make_float2(x, y), __NV_SATFINITE, __NV_E4M3);
        __nv_fp8x2_storage_t hi = __nv_cvt_float2_to_fp8x2(make_float2(z, w), __NV_SATFINITE, __NV_E4M3);
        dst8[lane + 32 * q] = (uint32_t)lo | ((uint32_t)hi << 16);
        srow[lane + 32 * q] = make_float4(x, y, z, w);
    }
    // bulk reduce-add the staged row into g_Ssum[cls]
    asm volatile("fence.proxy.async.shared::cta;" ::: "memory");
    __syncwarp();
    if (lane == 0) {
        bulk_red_add_f32(g_Ssum + (size_t)cls * DIM, smem_u32(stage[warp]), DIM * 4);
        bulk_commit();
        bulk_wait0();
    }
}

// ------------------------- kernel 2: fp8 GEMM upper triangle, flat 148-CTA schedule (verified) -------------------------
__global__ void __launch_bounds__(512, 1) supcon_main() {
    extern __shared__ char smem[];
    const int t = threadIdx.x, lane = t & 31, wid = t >> 5;
    const int warp_m = wid >> 2, warp_n = wid & 3;      // 4 x 4 warps, 32x32 tiles
    const int g0 = (NTILES_TOTAL * blockIdx.x) / NCTA;
    const int g1 = (NTILES_TOTAL * (blockIdx.x + 1)) / NCTA;
    const uint32_t sbase = smem_u32(smem);
    const uint32_t mb = sbase + OFF_MBAR;
    float* red = reinterpret_cast<float*>(smem + OFF_RED);   // [4][128]

    if (t == 0) { mbar_init(mb, 1); mbar_init(mb + 8, 1); }

    int ib0, c0;
    decode_tile(g0, ib0, c0);

    // load A tile for first iblk
    for (int f = t; f < 4096; f += 512) {
        int row = f >> 5, seg = f & 31;
        uint4 v = *reinterpret_cast<const uint4*>(g_A8 + (size_t)(ib0 * 128 + row) * DIM + seg * 16);
        *reinterpret_cast<uint4*>(smem + OFF_A + row * A_STRIDE + seg * 16) = v;
    }
    __syncthreads();   // A visible + mbars initialized

    // prologue: bulk-copy B tile of g0 into buf 0
    {
        const int jb = (ib0 + c0) & 63;
        if (t == 0) mbar_expect(mb, 128 * 512);
        if (t < 128)
            bulk_cp(sbase + OFF_B + t * A_STRIDE, g_A8 + (size_t)jb * (128 * DIM) + t * 512, 512, mb);
    }

    const uint32_t abase = sbase + OFF_A + (warp_m * 32 + (lane & 15)) * A_STRIDE + (lane >> 4) * 16;
    const uint32_t bb_lane = (((lane & 7) + ((lane >> 4) & 1) * 8) + warp_n * 32) * A_STRIDE + ((lane >> 3) & 1) * 16;

    float acc[2][4][4];
#pragma unroll
    for (int m = 0; m < 2; m++)
#pragma unroll
        for (int n = 0; n < 4; n++)
#pragma unroll
            for (int r = 0; r < 4; r++) acc[m][n][r] = 0.f;
    float z[4] = {0.f, 0.f, 0.f, 0.f};
    int cur_ib = ib0;

    for (int g = g0; g < g1; g++) {
        const int jl = g - g0;
        const int buf = jl & 1;
        int ib, c;
        decode_tile(g, ib, c);
        __syncthreads();                 // all warps done with buf^1 (tile g-1) and with old A
        if (g + 1 < g1) {
            int ibn, cn;
            decode_tile(g + 1, ibn, cn);
            const int jb = (ibn + cn) & 63;
            const uint32_t mbn = mb + 8 * (buf ^ 1);
            if (t == 0) mbar_expect(mbn, 128 * 512);
            if (t < 128)
                bulk_cp(sbase + OFF_B + (buf ^ 1) * TILE_BYTES + t * A_STRIDE,
                        g_A8 + (size_t)jb * (128 * DIM) + t * 512, 512, mbn);
        }
        if (ib != cur_ib) {
            // flush row sums for cur_ib
#pragma unroll
            for (int q = 0; q < 4; q++) {
                z[q] += __shfl_xor_sync(0xffffffffu, z[q], 1);
                z[q] += __shfl_xor_sync(0xffffffffu, z[q], 2);
            }
            if ((lane & 3) == 0) {
                int g4 = lane >> 2;
#pragma unroll
                for (int m = 0; m < 2; m++)
#pragma unroll
                    for (int h = 0; h < 2; h++)
                        red[warp_n * 128 + warp_m * 32 + m * 16 + h * 8 + g4] = z[2 * m + h];
            }
            __syncthreads();
            if (t < 128)
                atomicAdd(&g_Z[cur_ib * 128 + t],
                          (red[t] + red[128 + t] + red[256 + t] + red[384 + t]) * ESCALE);
            z[0] = z[1] = z[2] = z[3] = 0.f;
            // reload A for new iblk
            for (int f = t; f < 4096; f += 512) {
                int row = f >> 5, seg = f & 31;
                uint4 v = *reinterpret_cast<const uint4*>(g_A8 + (size_t)(ib * 128 + row) * DIM + seg * 16);
                *reinterpret_cast<uint4*>(smem + OFF_A + row * A_STRIDE + seg * 16) = v;
            }
            cur_ib = ib;
            __syncthreads();
        }
        mbar_wait(mb + 8 * buf, (jl >> 1) & 1);

        const uint32_t bb = sbase + OFF_B + buf * TILE_BYTES + bb_lane;
#pragma unroll
        for (int ks = 0; ks < 16; ks++) {
            const int koff = ks * 32;
            uint32_t a[2][4];
            ldm4(a[0], abase + koff);
            ldm4(a[1], abase + 16 * A_STRIDE + koff);
            uint32_t b[4][2];
#pragma unroll
            for (int p = 0; p < 2; p++) {
                uint32_t r4[4];
                ldm4(r4, bb + p * (16 * A_STRIDE) + koff);
                b[2 * p][0] = r4[0]; b[2 * p][1] = r4[1];
                b[2 * p + 1][0] = r4[2]; b[2 * p + 1][1] = r4[3];
            }
#pragma unroll
            for (int m = 0; m < 2; m++)
#pragma unroll
                for (int n = 0; n < 4; n++) qmma(acc[m][n], a[m], b[n]);
        }

        // ---- epilogue: f16x2 exp, row sums + REDG column sums ----
        {
            const int jblk = (ib + c) & 63;
            const bool dg = (c == 0);
            uint32_t zh[4] = {0, 0, 0, 0};
            uint32_t csh[4] = {0, 0, 0, 0};
#pragma unroll
            for (int m = 0; m < 2; m++)
#pragma unroll
                for (int n = 0; n < 4; n++)
#pragma unroll
                    for (int h = 0; h < 2; h++) {
                        float x0 = acc[m][n][2 * h]     * C_EXP - EBIAS;
                        float x1 = acc[m][n][2 * h + 1] * C_EXP - EBIAS;
                        if (dg) {
                            int rl = warp_m * 32 + m * 16 + h * 8 + (lane >> 2);
                            int cl0 = warp_n * 32 + n * 8 + (lane & 3) * 2;
                            if (rl == cl0)     x0 = -60.f;
                            if (rl == cl0 + 1) x1 = -60.f;
                        }
                        uint32_t e2 = ex2_h2(pack_h2(x0, x1));
                        zh[2 * m + h] = hadd2(zh[2 * m + h], e2);
                        csh[n] = hadd2(csh[n], e2);
                        acc[m][n][2 * h] = 0.f; acc[m][n][2 * h + 1] = 0.f;
                    }
#pragma unroll
            for (int q = 0; q < 4; q++) {
                float2 f = h2_to_f2(zh[q]);
                z[q] += f.x + f.y;
            }
            if (!dg) {
#pragma unroll
                for (int n = 0; n < 4; n++) {
                    uint32_t v = csh[n];
                    v = hadd2(v, __shfl_xor_sync(0xffffffffu, v, 4));
                    v = hadd2(v, __shfl_xor_sync(0xffffffffu, v, 8));
                    v = hadd2(v, __shfl_xor_sync(0xffffffffu, v, 16));
                    csh[n] = v;
                }
                if (lane < 4) {
                    float* zj = &g_Z[jblk * 128 + warp_n * 32 + lane * 2];
#pragma unroll
                    for (int n = 0; n < 4; n++) {
                        float2 f = h2_to_f2(csh[n]);
                        atomicAdd(&zj[n * 8 + 0], f.x * ESCALE);
                        atomicAdd(&zj[n * 8 + 1], f.y * ESCALE);
                    }
                }
            }
        }
    }

    // final flush of row sums for cur_ib
#pragma unroll
    for (int q = 0; q < 4; q++) {
        z[q] += __shfl_xor_sync(0xffffffffu, z[q], 1);
        z[q] += __shfl_xor_sync(0xffffffffu, z[q], 2);
    }
    __syncthreads();
    if ((lane & 3) == 0) {
        int g4 = lane >> 2;
#pragma unroll
        for (int m = 0; m < 2; m++)
#pragma unroll
            for (int h = 0; h < 2; h++)
                red[warp_n * 128 + warp_m * 32 + m * 16 + h * 8 + g4] = z[2 * m + h];
    }
    __syncthreads();
    if (t < 128)
        atomicAdd(&g_Z[cur_ib * 128 + t],
                  (red[t] + red[128 + t] + red[256 + t] + red[384 + t]) * ESCALE);
}

// ------------------------- kernel 3: per-row loss + last-block final write -------------------------
__global__ void finalize1(const int* __restrict__ labels, float* __restrict__ out) {
    __shared__ float wsum[8];
    const int t = threadIdx.x, lane = t & 31, wid = t >> 5;
    const int row = blockIdx.x * 8 + wid;
    const int b = row & (BATCH - 1);
    const int cls = labels[b];
    const uint2* arow = reinterpret_cast<const uint2*>(g_A) + (size_t)row * 128;
    const float4* srow = reinterpret_cast<const float4*>(g_Ssum) + (size_t)cls * 128;
    float dot = 0.f, self = 0.f;
#pragma unroll
    for (int q = 0; q < 4; q++) {
        uint2 u = arow[lane + 32 * q];
        float4 s = srow[lane + 32 * q];
        float2 a0 = __bfloat1622float2(*reinterpret_cast<const __nv_bfloat162*>(&u.x));
        float2 a1 = __bfloat1622float2(*reinterpret_cast<const __nv_bfloat162*>(&u.y));
        dot  += a0.x * s.x + a0.y * s.y + a1.x * s.z + a1.y * s.w;
        self += a0.x * a0.x + a0.y * a0.y + a1.x * a1.x + a1.y * a1.y;
    }
#pragma unroll
    for (int o = 16; o; o >>= 1) {
        dot  += __shfl_xor_sync(0xffffffffu, dot, o);
        self += __shfl_xor_sync(0xffffffffu, self, o);
    }
    if (lane == 0) {
        float C = 2.0f * (float)g_cnt[cls] - 1.0f;
        float Z = g_Z[row];
        float S = (dot - self) * INV_T;
        wsum[wid] = (S - C * logf(Z + 1e-8f)) / (C + 1e-8f);
    }
    __syncthreads();
    if (t == 0) {
        float bs = 0.f;
#pragma unroll
        for (int w = 0; w < 8; w++) bs += wsum[w];
        atomicAdd(&g_sum, bs);
        __threadfence();
        unsigned tk = atomicAdd(&g_done, 1u);
        if (tk == gridDim.x - 1) {   // all blocks' g_sum adds visible
            float s;
            asm volatile("ld.acquire.gpu.f32 %0, [%1];" : "=f"(s) : "l"(&g_sum));
            out[0] = -s / (float)NTOT;
        }
    }
}

// ------------------------- launch -------------------------
extern "C" void kernel_launch(void* const* d_in, const int* in_sizes, int n_in,
                              void* d_out, int out_size) {
    const float* feats = (const float*)d_in[0];
    const int* labels = (const int*)d_in[1];
    (void)in_sizes; (void)n_in; (void)out_size;

    void* p_ssum = nullptr; void* p_cnt = nullptr; void* p_sum = nullptr; void* p_done = nullptr;
    cudaGetSymbolAddress(&p_ssum, g_Ssum);
    cudaGetSymbolAddress(&p_cnt, g_cnt);
    cudaGetSymbolAddress(&p_sum, g_sum);
    cudaGetSymbolAddress(&p_done, g_done);
    cudaMemsetAsync(p_ssum, 0, (size_t)NCLS * DIM * sizeof(float));
    cudaMemsetAsync(p_cnt, 0, NCLS * sizeof(int));
    cudaMemsetAsync(p_sum, 0, sizeof(float));
    cudaMemsetAsync(p_done, 0, sizeof(unsigned));

    cudaFuncSetAttribute(supcon_main, cudaFuncAttributeMaxDynamicSharedMemorySize, SMEM_TOTAL);

    norm_kernel<<<NTOT / 8, 256>>>(feats, labels);
    supcon_main<<<NCTA, 512, SMEM_TOTAL>>>();
    finalize1<<<NTOT / 8, 256>>>(labels, (float*)d_out);
}